// round 1
// baseline (speedup 1.0000x reference)
#include <cuda_runtime.h>

// MeanPooling == batched GEMM + row scale.
// Inputs (metadata order):
//   d_in[0] doc_state      [B=32, L=2048, D=256] fp32
//   d_in[1] entity_mapping [B=32, E=256,  L=2048] fp32
//   d_in[2] entity_lens    [B=32, E=256] fp32
// Output: [B, E, D] fp32 = (emap @ doc) / lens
//
// Per batch: C[E,D] = A[E,L] * B[L,D], A=entity_mapping[b], B=doc_state[b].

#define B_DIM 32
#define E_DIM 256
#define L_DIM 2048
#define D_DIM 256

#define BM 64
#define BN 64
#define BK 16
#define TM 4
#define TN 4

__global__ __launch_bounds__(256, 4)
void mean_pool_gemm(const float* __restrict__ doc,
                    const float* __restrict__ emap,
                    const float* __restrict__ lens,
                    float* __restrict__ out)
{
    __shared__ float As[BK][BM];   // A tile, transposed (k-major)
    __shared__ float Bs[BK][BN];   // B tile

    const int b     = blockIdx.z;
    const int tileN = blockIdx.x * BN;
    const int tileM = blockIdx.y * BM;

    const float* A  = emap + (size_t)b * E_DIM * L_DIM;
    const float* Bm = doc  + (size_t)b * L_DIM * D_DIM;
    float*       C  = out  + (size_t)b * E_DIM * D_DIM;

    const int tid = threadIdx.x;          // 0..255
    const int tx  = tid & 15;             // 0..15 -> N direction
    const int ty  = tid >> 4;             // 0..15 -> M direction

    // Global->shared load mapping
    const int arow = tid >> 2;            // 0..63  (M row of A tile)
    const int akq  = (tid & 3) * 4;       // 0,4,8,12 (K quad)
    const int brow = tid >> 4;            // 0..15  (K row of B tile)
    const int bcol = (tid & 15) * 4;      // 0..60  (N quad)

    float acc[TM][TN];
    #pragma unroll
    for (int i = 0; i < TM; i++)
        #pragma unroll
        for (int j = 0; j < TN; j++)
            acc[i][j] = 0.0f;

    for (int k0 = 0; k0 < L_DIM; k0 += BK) {
        // Load A tile (BM x BK) transposed into As[k][m]
        float4 av = *reinterpret_cast<const float4*>(
            &A[(size_t)(tileM + arow) * L_DIM + k0 + akq]);
        As[akq + 0][arow] = av.x;
        As[akq + 1][arow] = av.y;
        As[akq + 2][arow] = av.z;
        As[akq + 3][arow] = av.w;

        // Load B tile (BK x BN)
        float4 bv = *reinterpret_cast<const float4*>(
            &Bm[(size_t)(k0 + brow) * D_DIM + tileN + bcol]);
        *reinterpret_cast<float4*>(&Bs[brow][bcol]) = bv;

        __syncthreads();

        #pragma unroll
        for (int kk = 0; kk < BK; kk++) {
            float4 af = *reinterpret_cast<const float4*>(&As[kk][ty * TM]);
            float4 bf = *reinterpret_cast<const float4*>(&Bs[kk][tx * TN]);
            float a[TM] = {af.x, af.y, af.z, af.w};
            float bb[TN] = {bf.x, bf.y, bf.z, bf.w};
            #pragma unroll
            for (int i = 0; i < TM; i++)
                #pragma unroll
                for (int j = 0; j < TN; j++)
                    acc[i][j] = fmaf(a[i], bb[j], acc[i][j]);
        }

        __syncthreads();
    }

    // Epilogue: divide by entity_lens, vectorized store
    #pragma unroll
    for (int i = 0; i < TM; i++) {
        const int e  = tileM + ty * TM + i;
        const float inv = 1.0f / lens[(size_t)b * E_DIM + e];
        float4 o;
        o.x = acc[i][0] * inv;
        o.y = acc[i][1] * inv;
        o.z = acc[i][2] * inv;
        o.w = acc[i][3] * inv;
        *reinterpret_cast<float4*>(&C[(size_t)e * D_DIM + tileN + tx * TN]) = o;
    }
}

extern "C" void kernel_launch(void* const* d_in, const int* in_sizes, int n_in,
                              void* d_out, int out_size)
{
    const float* doc  = (const float*)d_in[0];
    const float* emap = (const float*)d_in[1];
    const float* lens = (const float*)d_in[2];
    float* out = (float*)d_out;

    dim3 grid(D_DIM / BN, E_DIM / BM, B_DIM);   // (4, 4, 32)
    dim3 block(256);
    mean_pool_gemm<<<grid, block>>>(doc, emap, lens, out);
}

// round 3
// speedup vs baseline: 2.4993x; 2.4993x over previous
#include <cuda_runtime.h>
#include <cuda_bf16.h>
#include <cstdint>

// MeanPooling == batched GEMM + row scale, via mma.sync bf16 hi/lo split.
//   d_in[0] doc_state      [B=32, L=2048, D=256] fp32   (B operand)
//   d_in[1] entity_mapping [B=32, E=256,  L=2048] fp32  (A operand)
//   d_in[2] entity_lens    [B=32, E=256] fp32
// Output [B, E, D] fp32 = (emap @ doc) / lens
//
// x = hi + lo (bf16 each); x*y ~= hi*hi + hi*lo + lo*hi (fp32 accum).
// CTA tile: 128(M=E) x 128(N=D), K chunks of 32, double-buffered smem,
// register-prefetch of next chunk overlapping HMMA compute.

#define BATCH 32
#define E_DIM 256
#define L_DIM 2048
#define D_DIM 256

#define TILE_M 128
#define TILE_N 128
#define CHUNK 32
#define NCHUNK (L_DIM / CHUNK)      // 64

// smem layout (bf16, padded strides for conflict-free ldmatrix)
#define A_STRIDE 40                  // bf16 per A row (80 bytes, 16B-aligned, odd*16)
#define B_STRIDE 136                 // bf16 per B row (272 bytes)
#define A_SPLIT_BYTES (TILE_M * A_STRIDE * 2)   // 10240
#define B_SPLIT_BYTES (CHUNK * B_STRIDE * 2)    // 8704
#define OFF_A_HI 0
#define OFF_A_LO (A_SPLIT_BYTES)
#define OFF_B_HI (2 * A_SPLIT_BYTES)
#define OFF_B_LO (2 * A_SPLIT_BYTES + B_SPLIT_BYTES)
#define STAGE_BYTES (2 * A_SPLIT_BYTES + 2 * B_SPLIT_BYTES)  // 37888
#define SMEM_TOTAL (2 * STAGE_BYTES)                          // 75776

static __device__ __forceinline__ uint32_t smem_u32(const void* p) {
    uint32_t a;
    asm("{ .reg .u64 t; cvta.to.shared.u64 t, %1; cvt.u32.u64 %0, t; }"
        : "=r"(a) : "l"(p));
    return a;
}

#define LDSM_X4(r0, r1, r2, r3, addr) \
    asm volatile("ldmatrix.sync.aligned.m8n8.x4.shared.b16 {%0,%1,%2,%3}, [%4];" \
                 : "=r"(r0), "=r"(r1), "=r"(r2), "=r"(r3) : "r"(addr))

#define LDSM_X4_T(r0, r1, r2, r3, addr) \
    asm volatile("ldmatrix.sync.aligned.m8n8.x4.trans.shared.b16 {%0,%1,%2,%3}, [%4];" \
                 : "=r"(r0), "=r"(r1), "=r"(r2), "=r"(r3) : "r"(addr))

#define MMA16816(d, a0, a1, a2, a3, b0, b1) \
    asm volatile("mma.sync.aligned.m16n8k16.row.col.f32.bf16.bf16.f32 " \
                 "{%0,%1,%2,%3}, {%4,%5,%6,%7}, {%8,%9}, {%0,%1,%2,%3};" \
                 : "+f"((d)[0]), "+f"((d)[1]), "+f"((d)[2]), "+f"((d)[3]) \
                 : "r"(a0), "r"(a1), "r"(a2), "r"(a3), "r"(b0), "r"(b1))

static __device__ __forceinline__ void split2(float x, float y,
                                              uint32_t& hi, uint32_t& lo)
{
    __nv_bfloat16 hx = __float2bfloat16(x);
    __nv_bfloat16 hy = __float2bfloat16(y);
    __nv_bfloat16 lx = __float2bfloat16(x - __bfloat162float(hx));
    __nv_bfloat16 ly = __float2bfloat16(y - __bfloat162float(hy));
    hi = (uint32_t)__bfloat16_as_ushort(hx) | ((uint32_t)__bfloat16_as_ushort(hy) << 16);
    lo = (uint32_t)__bfloat16_as_ushort(lx) | ((uint32_t)__bfloat16_as_ushort(ly) << 16);
}

__global__ void __launch_bounds__(256, 1)
mean_pool_hmma(const float* __restrict__ doc,
               const float* __restrict__ emap,
               const float* __restrict__ lens,
               float* __restrict__ out)
{
    extern __shared__ char smem[];
    const uint32_t sbase = smem_u32(smem);

    const int tid = threadIdx.x;
    const int wid = tid >> 5;
    const int lid = tid & 31;
    const int wm  = wid & 3;        // 4 warps in M
    const int wn  = wid >> 2;       // 2 warps in N

    const int b     = blockIdx.z;
    const int tileM = blockIdx.y * TILE_M;
    const int tileN = blockIdx.x * TILE_N;

    const float* A  = emap + (size_t)b * E_DIM * L_DIM + (size_t)tileM * L_DIM;
    const float* Bm = doc  + (size_t)b * L_DIM * D_DIM + tileN;
    float*       C  = out  + (size_t)b * E_DIM * D_DIM;

    // gmem -> reg load mapping (per chunk of K=32)
    const int a_row = tid >> 1;         // 0..127 (M)
    const int a_k   = (tid & 1) * 16;   // 0/16   (K)
    const int b_row = tid >> 3;         // 0..31  (K)
    const int b_n   = (tid & 7) * 16;   // 0..112 (N)

    float acc[2][8][4] = {};            // [m-tile][n8-tile][frag]
    float4 av[4], bv[4];

    // ldmatrix lane addressing (shared across both splits / stages)
    const uint32_t a_lrow = (uint32_t)(wm * 32 + (lid & 15));
    const uint32_t a_lcol = (uint32_t)((lid >> 4) * 16);         // bytes
    const uint32_t b_lrow = (uint32_t)(lid & 15);
    const uint32_t b_lcol = (uint32_t)(wn * 128 + (lid >> 4) * 16);  // bytes

    // ---- prologue: load + stage chunk 0 ----
    #pragma unroll
    for (int i = 0; i < 4; i++)
        av[i] = *reinterpret_cast<const float4*>(&A[(size_t)a_row * L_DIM + a_k + 4 * i]);
    #pragma unroll
    for (int i = 0; i < 4; i++)
        bv[i] = *reinterpret_cast<const float4*>(&Bm[(size_t)b_row * D_DIM + b_n + 4 * i]);

    {
        char* st = smem;  // stage 0
        uint32_t h[8], l[8];
        #pragma unroll
        for (int i = 0; i < 4; i++) {
            split2(av[i].x, av[i].y, h[2 * i], l[2 * i]);
            split2(av[i].z, av[i].w, h[2 * i + 1], l[2 * i + 1]);
        }
        char* pa = st + OFF_A_HI + a_row * (A_STRIDE * 2) + a_k * 2;
        *reinterpret_cast<uint4*>(pa)      = make_uint4(h[0], h[1], h[2], h[3]);
        *reinterpret_cast<uint4*>(pa + 16) = make_uint4(h[4], h[5], h[6], h[7]);
        pa += (OFF_A_LO - OFF_A_HI);
        *reinterpret_cast<uint4*>(pa)      = make_uint4(l[0], l[1], l[2], l[3]);
        *reinterpret_cast<uint4*>(pa + 16) = make_uint4(l[4], l[5], l[6], l[7]);

        #pragma unroll
        for (int i = 0; i < 4; i++) {
            split2(bv[i].x, bv[i].y, h[2 * i], l[2 * i]);
            split2(bv[i].z, bv[i].w, h[2 * i + 1], l[2 * i + 1]);
        }
        char* pb = st + OFF_B_HI + b_row * (B_STRIDE * 2) + b_n * 2;
        *reinterpret_cast<uint4*>(pb)      = make_uint4(h[0], h[1], h[2], h[3]);
        *reinterpret_cast<uint4*>(pb + 16) = make_uint4(h[4], h[5], h[6], h[7]);
        pb += (OFF_B_LO - OFF_B_HI);
        *reinterpret_cast<uint4*>(pb)      = make_uint4(l[0], l[1], l[2], l[3]);
        *reinterpret_cast<uint4*>(pb + 16) = make_uint4(l[4], l[5], l[6], l[7]);
    }
    __syncthreads();

    for (int c = 0; c < NCHUNK; c++) {
        const int s = c & 1;

        // prefetch next chunk into registers (overlaps HMMA below)
        if (c + 1 < NCHUNK) {
            const int k0 = (c + 1) * CHUNK;
            #pragma unroll
            for (int i = 0; i < 4; i++)
                av[i] = *reinterpret_cast<const float4*>(
                    &A[(size_t)a_row * L_DIM + k0 + a_k + 4 * i]);
            #pragma unroll
            for (int i = 0; i < 4; i++)
                bv[i] = *reinterpret_cast<const float4*>(
                    &Bm[(size_t)(k0 + b_row) * D_DIM + b_n + 4 * i]);
        }

        // ---- compute on stage s ----
        const uint32_t stg  = sbase + (uint32_t)(s * STAGE_BYTES);
        const uint32_t aHi  = stg + OFF_A_HI;
        const uint32_t aLo  = stg + OFF_A_LO;
        const uint32_t bHi  = stg + OFF_B_HI;
        const uint32_t bLo  = stg + OFF_B_LO;

        #pragma unroll
        for (int ko = 0; ko < 2; ko++) {            // two k16 steps
            const uint32_t akb = a_lcol + (uint32_t)(ko * 32);  // k byte offset
            uint32_t ah[2][4], al[2][4];
            #pragma unroll
            for (int mi = 0; mi < 2; mi++) {
                const uint32_t ao = (a_lrow + mi * 16) * (A_STRIDE * 2) + akb;
                LDSM_X4(ah[mi][0], ah[mi][1], ah[mi][2], ah[mi][3], aHi + ao);
                LDSM_X4(al[mi][0], al[mi][1], al[mi][2], al[mi][3], aLo + ao);
            }
            #pragma unroll
            for (int nt = 0; nt < 4; nt++) {        // four n16 tiles per warp
                const uint32_t bo = (b_lrow + (uint32_t)(ko * 16)) * (B_STRIDE * 2)
                                    + b_lcol + (uint32_t)(nt * 32);
                uint32_t bh0, bh1, bh2, bh3, bl0, bl1, bl2, bl3;
                LDSM_X4_T(bh0, bh1, bh2, bh3, bHi + bo);
                LDSM_X4_T(bl0, bl1, bl2, bl3, bLo + bo);
                #pragma unroll
                for (int mi = 0; mi < 2; mi++) {
                    float* d0 = acc[mi][nt * 2];
                    float* d1 = acc[mi][nt * 2 + 1];
                    MMA16816(d0, ah[mi][0], ah[mi][1], ah[mi][2], ah[mi][3], bh0, bh1);
                    MMA16816(d0, ah[mi][0], ah[mi][1], ah[mi][2], ah[mi][3], bl0, bl1);
                    MMA16816(d0, al[mi][0], al[mi][1], al[mi][2], al[mi][3], bh0, bh1);
                    MMA16816(d1, ah[mi][0], ah[mi][1], ah[mi][2], ah[mi][3], bh2, bh3);
                    MMA16816(d1, ah[mi][0], ah[mi][1], ah[mi][2], ah[mi][3], bl2, bl3);
                    MMA16816(d1, al[mi][0], al[mi][1], al[mi][2], al[mi][3], bh2, bh3);
                }
            }
        }

        // ---- stage chunk c+1 into the other buffer ----
        if (c + 1 < NCHUNK) {
            char* st = smem + (s ^ 1) * STAGE_BYTES;
            uint32_t h[8], l[8];
            #pragma unroll
            for (int i = 0; i < 4; i++) {
                split2(av[i].x, av[i].y, h[2 * i], l[2 * i]);
                split2(av[i].z, av[i].w, h[2 * i + 1], l[2 * i + 1]);
            }
            char* pa = st + OFF_A_HI + a_row * (A_STRIDE * 2) + a_k * 2;
            *reinterpret_cast<uint4*>(pa)      = make_uint4(h[0], h[1], h[2], h[3]);
            *reinterpret_cast<uint4*>(pa + 16) = make_uint4(h[4], h[5], h[6], h[7]);
            pa += (OFF_A_LO - OFF_A_HI);
            *reinterpret_cast<uint4*>(pa)      = make_uint4(l[0], l[1], l[2], l[3]);
            *reinterpret_cast<uint4*>(pa + 16) = make_uint4(l[4], l[5], l[6], l[7]);

            #pragma unroll
            for (int i = 0; i < 4; i++) {
                split2(bv[i].x, bv[i].y, h[2 * i], l[2 * i]);
                split2(bv[i].z, bv[i].w, h[2 * i + 1], l[2 * i + 1]);
            }
            char* pb = st + OFF_B_HI + b_row * (B_STRIDE * 2) + b_n * 2;
            *reinterpret_cast<uint4*>(pb)      = make_uint4(h[0], h[1], h[2], h[3]);
            *reinterpret_cast<uint4*>(pb + 16) = make_uint4(h[4], h[5], h[6], h[7]);
            pb += (OFF_B_LO - OFF_B_HI);
            *reinterpret_cast<uint4*>(pb)      = make_uint4(l[0], l[1], l[2], l[3]);
            *reinterpret_cast<uint4*>(pb + 16) = make_uint4(l[4], l[5], l[6], l[7]);
        }
        __syncthreads();
    }

    // ---- epilogue: scale by 1/len, store ----
    #pragma unroll
    for (int mi = 0; mi < 2; mi++) {
        const int r0 = tileM + wm * 32 + mi * 16 + (lid >> 2);
        const int r1 = r0 + 8;
        const float inv0 = 1.0f / lens[(size_t)b * E_DIM + r0];
        const float inv1 = 1.0f / lens[(size_t)b * E_DIM + r1];
        #pragma unroll
        for (int j = 0; j < 8; j++) {
            const int col = tileN + wn * 64 + j * 8 + (lid & 3) * 2;
            float2 o0 = make_float2(acc[mi][j][0] * inv0, acc[mi][j][1] * inv0);
            float2 o1 = make_float2(acc[mi][j][2] * inv1, acc[mi][j][3] * inv1);
            *reinterpret_cast<float2*>(&C[(size_t)r0 * D_DIM + col]) = o0;
            *reinterpret_cast<float2*>(&C[(size_t)r1 * D_DIM + col]) = o1;
        }
    }
}

extern "C" void kernel_launch(void* const* d_in, const int* in_sizes, int n_in,
                              void* d_out, int out_size)
{
    const float* doc  = (const float*)d_in[0];
    const float* emap = (const float*)d_in[1];
    const float* lens = (const float*)d_in[2];
    float* out = (float*)d_out;

    cudaFuncSetAttribute(mean_pool_hmma,
                         cudaFuncAttributeMaxDynamicSharedMemorySize, SMEM_TOTAL);

    dim3 grid(D_DIM / TILE_N, E_DIM / TILE_M, BATCH);   // (2, 2, 32) = 128 CTAs
    mean_pool_hmma<<<grid, 256, SMEM_TOTAL>>>(doc, emap, lens, out);
}

// round 4
// speedup vs baseline: 2.6910x; 1.0767x over previous
#include <cuda_runtime.h>
#include <cuda_bf16.h>
#include <cstdint>

// MeanPooling == batched GEMM + row scale, via mma.sync bf16 hi/lo split.
//   d_in[0] doc_state      [B=32, L=2048, D=256] fp32   (B operand)
//   d_in[1] entity_mapping [B=32, E=256,  L=2048] fp32  (A operand)
//   d_in[2] entity_lens    [B=32, E=256] fp32
// Output [B, E, D] fp32 = (emap @ doc) / lens
//
// x = hi + lo (bf16); x*y ~= hi*hi + hi*lo + lo*hi (fp32 accum).
// CTA tile 128(M) x 64(N), K chunks of 32, double-buffered smem,
// register-prefetch. 256 CTAs, 2 CTAs/SM for cross-CTA latency hiding.

#define BATCH 32
#define E_DIM 256
#define L_DIM 2048
#define D_DIM 256

#define TILE_M 128
#define TILE_N 64
#define CHUNK 32
#define NCHUNK (L_DIM / CHUNK)      // 64

// smem (bf16, strides chosen so consecutive rows shift 16B mod 128 -> no
// ldmatrix bank conflicts): A stride 40 bf16 = 80B, B stride 72 bf16 = 144B.
#define A_STRIDE 40
#define B_STRIDE 72
#define A_SPLIT_BYTES (TILE_M * A_STRIDE * 2)   // 10240
#define B_SPLIT_BYTES (CHUNK * B_STRIDE * 2)    // 4608
#define OFF_A_HI 0
#define OFF_A_LO (A_SPLIT_BYTES)
#define OFF_B_HI (2 * A_SPLIT_BYTES)
#define OFF_B_LO (2 * A_SPLIT_BYTES + B_SPLIT_BYTES)
#define STAGE_BYTES (2 * A_SPLIT_BYTES + 2 * B_SPLIT_BYTES)  // 29696
#define SMEM_TOTAL (2 * STAGE_BYTES)                          // 59392

static __device__ __forceinline__ uint32_t smem_u32(const void* p) {
    uint32_t a;
    asm("{ .reg .u64 t; cvta.to.shared.u64 t, %1; cvt.u32.u64 %0, t; }"
        : "=r"(a) : "l"(p));
    return a;
}

#define LDSM_X4(r0, r1, r2, r3, addr) \
    asm volatile("ldmatrix.sync.aligned.m8n8.x4.shared.b16 {%0,%1,%2,%3}, [%4];" \
                 : "=r"(r0), "=r"(r1), "=r"(r2), "=r"(r3) : "r"(addr))

#define LDSM_X4_T(r0, r1, r2, r3, addr) \
    asm volatile("ldmatrix.sync.aligned.m8n8.x4.trans.shared.b16 {%0,%1,%2,%3}, [%4];" \
                 : "=r"(r0), "=r"(r1), "=r"(r2), "=r"(r3) : "r"(addr))

#define MMA16816(d, a0, a1, a2, a3, b0, b1) \
    asm volatile("mma.sync.aligned.m16n8k16.row.col.f32.bf16.bf16.f32 " \
                 "{%0,%1,%2,%3}, {%4,%5,%6,%7}, {%8,%9}, {%0,%1,%2,%3};" \
                 : "+f"((d)[0]), "+f"((d)[1]), "+f"((d)[2]), "+f"((d)[3]) \
                 : "r"(a0), "r"(a1), "r"(a2), "r"(a3), "r"(b0), "r"(b1))

static __device__ __forceinline__ void split2(float x, float y,
                                              uint32_t& hi, uint32_t& lo)
{
    __nv_bfloat16 hx = __float2bfloat16(x);
    __nv_bfloat16 hy = __float2bfloat16(y);
    __nv_bfloat16 lx = __float2bfloat16(x - __bfloat162float(hx));
    __nv_bfloat16 ly = __float2bfloat16(y - __bfloat162float(hy));
    hi = (uint32_t)__bfloat16_as_ushort(hx) | ((uint32_t)__bfloat16_as_ushort(hy) << 16);
    lo = (uint32_t)__bfloat16_as_ushort(lx) | ((uint32_t)__bfloat16_as_ushort(ly) << 16);
}

__global__ void __launch_bounds__(256, 2)
mean_pool_hmma(const float* __restrict__ doc,
               const float* __restrict__ emap,
               const float* __restrict__ lens,
               float* __restrict__ out)
{
    extern __shared__ char smem[];
    const uint32_t sbase = smem_u32(smem);

    const int tid = threadIdx.x;
    const int wid = tid >> 5;
    const int lid = tid & 31;
    const int wm  = wid & 3;        // 4 warps in M (32 rows each)
    const int wn  = wid >> 2;       // 2 warps in N (32 cols each)

    const int b     = blockIdx.z;
    const int tileM = blockIdx.y * TILE_M;
    const int tileN = blockIdx.x * TILE_N;

    const float* A  = emap + (size_t)b * E_DIM * L_DIM + (size_t)tileM * L_DIM;
    const float* Bm = doc  + (size_t)b * L_DIM * D_DIM + tileN;
    float*       C  = out  + (size_t)b * E_DIM * D_DIM;

    // gmem -> reg load mapping (per chunk of K=32)
    const int a_row = tid >> 1;         // 0..127 (M), 16 floats each
    const int a_k   = (tid & 1) * 16;   // 0/16
    const int b_row = tid >> 3;         // 0..31  (K), 8 floats each
    const int b_n   = (tid & 7) * 8;    // 0..56  (N)

    float acc[2][4][4] = {};            // [m16-tile][n8-tile][frag]
    float4 av[4];
    float4 bv[2];

    // ldmatrix lane addressing
    const uint32_t a_lrow = (uint32_t)(wm * 32 + (lid & 15));
    const uint32_t a_lcol = (uint32_t)((lid >> 4) * 16);             // bytes
    const uint32_t b_lrow = (uint32_t)(lid & 15);
    const uint32_t b_lcol = (uint32_t)(wn * 64 + (lid >> 4) * 16);   // bytes

    // ---- prologue: load + stage chunk 0 ----
    #pragma unroll
    for (int i = 0; i < 4; i++)
        av[i] = *reinterpret_cast<const float4*>(&A[(size_t)a_row * L_DIM + a_k + 4 * i]);
    #pragma unroll
    for (int i = 0; i < 2; i++)
        bv[i] = *reinterpret_cast<const float4*>(&Bm[(size_t)b_row * D_DIM + b_n + 4 * i]);

    {
        char* st = smem;  // stage 0
        uint32_t h[8], l[8];
        #pragma unroll
        for (int i = 0; i < 4; i++) {
            split2(av[i].x, av[i].y, h[2 * i], l[2 * i]);
            split2(av[i].z, av[i].w, h[2 * i + 1], l[2 * i + 1]);
        }
        char* pa = st + OFF_A_HI + a_row * (A_STRIDE * 2) + a_k * 2;
        *reinterpret_cast<uint4*>(pa)      = make_uint4(h[0], h[1], h[2], h[3]);
        *reinterpret_cast<uint4*>(pa + 16) = make_uint4(h[4], h[5], h[6], h[7]);
        pa += (OFF_A_LO - OFF_A_HI);
        *reinterpret_cast<uint4*>(pa)      = make_uint4(l[0], l[1], l[2], l[3]);
        *reinterpret_cast<uint4*>(pa + 16) = make_uint4(l[4], l[5], l[6], l[7]);

        #pragma unroll
        for (int i = 0; i < 2; i++) {
            split2(bv[i].x, bv[i].y, h[2 * i], l[2 * i]);
            split2(bv[i].z, bv[i].w, h[2 * i + 1], l[2 * i + 1]);
        }
        char* pb = st + OFF_B_HI + b_row * (B_STRIDE * 2) + b_n * 2;
        *reinterpret_cast<uint4*>(pb) = make_uint4(h[0], h[1], h[2], h[3]);
        pb += (OFF_B_LO - OFF_B_HI);
        *reinterpret_cast<uint4*>(pb) = make_uint4(l[0], l[1], l[2], l[3]);
    }
    __syncthreads();

    for (int c = 0; c < NCHUNK; c++) {
        const int s = c & 1;

        // prefetch next chunk into registers (overlaps HMMA below)
        if (c + 1 < NCHUNK) {
            const int k0 = (c + 1) * CHUNK;
            #pragma unroll
            for (int i = 0; i < 4; i++)
                av[i] = *reinterpret_cast<const float4*>(
                    &A[(size_t)a_row * L_DIM + k0 + a_k + 4 * i]);
            #pragma unroll
            for (int i = 0; i < 2; i++)
                bv[i] = *reinterpret_cast<const float4*>(
                    &Bm[(size_t)(k0 + b_row) * D_DIM + b_n + 4 * i]);
        }

        // ---- compute on stage s ----
        const uint32_t stg = sbase + (uint32_t)(s * STAGE_BYTES);
        const uint32_t aHi = stg + OFF_A_HI;
        const uint32_t aLo = stg + OFF_A_LO;
        const uint32_t bHi = stg + OFF_B_HI;
        const uint32_t bLo = stg + OFF_B_LO;

        #pragma unroll
        for (int ko = 0; ko < 2; ko++) {            // two k16 steps
            const uint32_t akb = a_lcol + (uint32_t)(ko * 32);
            uint32_t ah[2][4], al[2][4];
            #pragma unroll
            for (int mi = 0; mi < 2; mi++) {
                const uint32_t ao = (a_lrow + mi * 16) * (A_STRIDE * 2) + akb;
                LDSM_X4(ah[mi][0], ah[mi][1], ah[mi][2], ah[mi][3], aHi + ao);
                LDSM_X4(al[mi][0], al[mi][1], al[mi][2], al[mi][3], aLo + ao);
            }
            #pragma unroll
            for (int nt = 0; nt < 2; nt++) {        // two n16 tiles per warp
                const uint32_t bo = (b_lrow + (uint32_t)(ko * 16)) * (B_STRIDE * 2)
                                    + b_lcol + (uint32_t)(nt * 32);
                uint32_t bh0, bh1, bh2, bh3, bl0, bl1, bl2, bl3;
                LDSM_X4_T(bh0, bh1, bh2, bh3, bHi + bo);
                LDSM_X4_T(bl0, bl1, bl2, bl3, bLo + bo);
                #pragma unroll
                for (int mi = 0; mi < 2; mi++) {
                    float* d0 = acc[mi][nt * 2];
                    float* d1 = acc[mi][nt * 2 + 1];
                    MMA16816(d0, ah[mi][0], ah[mi][1], ah[mi][2], ah[mi][3], bh0, bh1);
                    MMA16816(d0, ah[mi][0], ah[mi][1], ah[mi][2], ah[mi][3], bl0, bl1);
                    MMA16816(d0, al[mi][0], al[mi][1], al[mi][2], al[mi][3], bh0, bh1);
                    MMA16816(d1, ah[mi][0], ah[mi][1], ah[mi][2], ah[mi][3], bh2, bh3);
                    MMA16816(d1, ah[mi][0], ah[mi][1], ah[mi][2], ah[mi][3], bl2, bl3);
                    MMA16816(d1, al[mi][0], al[mi][1], al[mi][2], al[mi][3], bh2, bh3);
                }
            }
        }

        // ---- stage chunk c+1 into the other buffer ----
        if (c + 1 < NCHUNK) {
            char* st = smem + (s ^ 1) * STAGE_BYTES;
            uint32_t h[8], l[8];
            #pragma unroll
            for (int i = 0; i < 4; i++) {
                split2(av[i].x, av[i].y, h[2 * i], l[2 * i]);
                split2(av[i].z, av[i].w, h[2 * i + 1], l[2 * i + 1]);
            }
            char* pa = st + OFF_A_HI + a_row * (A_STRIDE * 2) + a_k * 2;
            *reinterpret_cast<uint4*>(pa)      = make_uint4(h[0], h[1], h[2], h[3]);
            *reinterpret_cast<uint4*>(pa + 16) = make_uint4(h[4], h[5], h[6], h[7]);
            pa += (OFF_A_LO - OFF_A_HI);
            *reinterpret_cast<uint4*>(pa)      = make_uint4(l[0], l[1], l[2], l[3]);
            *reinterpret_cast<uint4*>(pa + 16) = make_uint4(l[4], l[5], l[6], l[7]);

            #pragma unroll
            for (int i = 0; i < 2; i++) {
                split2(bv[i].x, bv[i].y, h[2 * i], l[2 * i]);
                split2(bv[i].z, bv[i].w, h[2 * i + 1], l[2 * i + 1]);
            }
            char* pb = st + OFF_B_HI + b_row * (B_STRIDE * 2) + b_n * 2;
            *reinterpret_cast<uint4*>(pb) = make_uint4(h[0], h[1], h[2], h[3]);
            pb += (OFF_B_LO - OFF_B_HI);
            *reinterpret_cast<uint4*>(pb) = make_uint4(l[0], l[1], l[2], l[3]);
        }
        __syncthreads();
    }

    // ---- epilogue: scale by 1/len, store ----
    #pragma unroll
    for (int mi = 0; mi < 2; mi++) {
        const int r0 = tileM + wm * 32 + mi * 16 + (lid >> 2);
        const int r1 = r0 + 8;
        const float inv0 = 1.0f / lens[(size_t)b * E_DIM + r0];
        const float inv1 = 1.0f / lens[(size_t)b * E_DIM + r1];
        #pragma unroll
        for (int j = 0; j < 4; j++) {
            const int col = tileN + wn * 32 + j * 8 + (lid & 3) * 2;
            float2 o0 = make_float2(acc[mi][j][0] * inv0, acc[mi][j][1] * inv0);
            float2 o1 = make_float2(acc[mi][j][2] * inv1, acc[mi][j][3] * inv1);
            *reinterpret_cast<float2*>(&C[(size_t)r0 * D_DIM + col]) = o0;
            *reinterpret_cast<float2*>(&C[(size_t)r1 * D_DIM + col]) = o1;
        }
    }
}

extern "C" void kernel_launch(void* const* d_in, const int* in_sizes, int n_in,
                              void* d_out, int out_size)
{
    const float* doc  = (const float*)d_in[0];
    const float* emap = (const float*)d_in[1];
    const float* lens = (const float*)d_in[2];
    float* out = (float*)d_out;

    cudaFuncSetAttribute(mean_pool_hmma,
                         cudaFuncAttributeMaxDynamicSharedMemorySize, SMEM_TOTAL);

    dim3 grid(D_DIM / TILE_N, E_DIM / TILE_M, BATCH);   // (4, 2, 32) = 256 CTAs
    mean_pool_hmma<<<grid, 256, SMEM_TOTAL>>>(doc, emap, lens, out);
}